// round 15
// baseline (speedup 1.0000x reference)
#include <cuda_runtime.h>
#include <cuda_fp16.h>

#define BB 8192
#define NW 4
#define LL 16
#define EE 128
#define HH 128
#define VV 64
#define BN_TOT (BB*NW)
#define G4H 512

typedef unsigned int u32;

// G pre-packed f16, fragment-major: off = v*1032 + q*512 + st*128 + g*32 + t4*8 + b*4 + e*2
__device__ __align__(16) unsigned char g_Gh[VV * 1032];
__device__ __align__(16) __half g_reps_h[(size_t)BN_TOT * HH];
__device__ int g_perm[BN_TOT];
__device__ int g_cursor[16];
__device__ int g_hist[16];
__device__ unsigned int g_tick;

// ---- dynamic smem map (bytes) ----
#define SM_W    0          // W_hh f16 [512][128], 256B rows, XOR swizzle   (131072)
#define SM_H    131072     // h f16 [128][128], 256B rows, XOR swizzle      (32768)
#define SM_WID  163840     // u8 [128][16]                                  (2048)
#define SM_LEN  165888     // u8 [128]
#define SM_BYTES 166016

__device__ __forceinline__ float sigm_exact(float x) { return __fdividef(1.f, 1.f + __expf(-x)); }

__device__ __forceinline__ u32 s2u(const void* p) {
    u32 a; asm("{.reg .u64 t; cvta.to.shared.u64 t, %1; cvt.u32.u64 %0, t;}" : "=r"(a) : "l"(p));
    return a;
}
__device__ __forceinline__ void ldsm4(u32* r, u32 addr) {
    asm volatile("ldmatrix.sync.aligned.m8n8.x4.shared.b16 {%0,%1,%2,%3}, [%4];"
        : "=r"(r[0]), "=r"(r[1]), "=r"(r[2]), "=r"(r[3]) : "r"(addr));
}
__device__ __forceinline__ void mma16816(float* c, const u32* a, const u32* b) {
    asm volatile("mma.sync.aligned.m16n8k16.row.col.f32.f16.f16.f32 "
        "{%0,%1,%2,%3}, {%4,%5,%6,%7}, {%8,%9}, {%0,%1,%2,%3};"
        : "+f"(c[0]), "+f"(c[1]), "+f"(c[2]), "+f"(c[3])
        : "r"(a[0]), "r"(a[1]), "r"(a[2]), "r"(a[3]), "r"(b[0]), "r"(b[1]));
}
__device__ __forceinline__ u32 packh2(float a, float b) {
    __half2 h = __floats2half2_rn(a, b);
    return *(u32*)&h;
}
__device__ __forceinline__ float2 h22f2(u32 x) { return __half22float2(*(__half2*)&x); }
__device__ __forceinline__ u32 tanh2(u32 x) {
    u32 y; asm("tanh.approx.f16x2 %0, %1;" : "=r"(y) : "r"(x)); return y;
}
__device__ __forceinline__ u32 mul2(u32 a, u32 b) {
    __half2 r = __hmul2(*(__half2*)&a, *(__half2*)&b); return *(u32*)&r;
}
__device__ __forceinline__ u32 sig2(u32 x) {   // sigmoid(x) = 0.5*tanh(0.5x)+0.5, f16x2
    const u32 k05 = 0x38003800u;
    u32 t = tanh2(mul2(x, k05));
    __half2 r = __hfma2(*(__half2*)&t, *(__half2*)&k05, *(__half2*)&k05);
    return *(u32*)&r;
}

// ---- fused: blocks 0..63 packed G; blocks 64..127 histogram; last block scans ----
__global__ void k_pre1(const int* __restrict__ lengths,
                       const float* __restrict__ emb, const float* __restrict__ Wih,
                       const float* __restrict__ bih, const float* __restrict__ bhh) {
    int tid = threadIdx.x;
    if (blockIdx.x < 64) {
        int v = blockIdx.x, j = tid;
        const float* e = emb + v * EE;
        const float* w = Wih + j * EE;
        float s = bih[j] + bhh[j];
#pragma unroll 8
        for (int k = 0; k < EE; ++k) s = fmaf(e[k], w[k], s);
        int g = j >> 7, q = (j >> 6) & 1, u = j & 63;
        int st = u >> 4, b = (u >> 3) & 1, t4 = (u >> 1) & 3, ee = u & 1;
        int off = v * 1032 + q * 512 + st * 128 + g * 32 + t4 * 8 + b * 4 + ee * 2;
        *(__half*)(g_Gh + off) = __float2half_rn(s);
    } else {
        __shared__ int sh[16];
        if (tid < 16) sh[tid] = 0;
        __syncthreads();
        int bn = (blockIdx.x - 64) * 512 + tid;
        atomicAdd(&sh[16 - lengths[bn]], 1);
        __syncthreads();
        if (tid < 16) atomicAdd(&g_hist[tid], sh[tid]);
        __syncthreads();
        if (tid == 0 && (atomicAdd(&g_tick, 1u) & 63u) == 63u) {
            int cum = 0;
            for (int b2 = 0; b2 < 16; ++b2) {
                g_cursor[b2] = cum; cum += g_hist[b2]; g_hist[b2] = 0;
            }
        }
    }
}

__global__ void k_scatter(const int* __restrict__ lengths) {
    __shared__ int cnt[16], base[16];
    int tid = threadIdx.x;
    if (tid < 16) cnt[tid] = 0;
    __syncthreads();
    int bn = blockIdx.x * 256 + tid;
    int bin = 16 - lengths[bn];
    int rank = atomicAdd(&cnt[bin], 1);
    __syncthreads();
    if (tid < 16) base[tid] = atomicAdd(&g_cursor[tid], cnt[tid]);
    __syncthreads();
    g_perm[base[bin] + rank] = bn;
}

// ---- HMMA LSTM: M=32 rows/warp (2 m16 tiles), gate-split pairs, 8 warps ----
// CTA = 128 rows, 8 warps = 4 pairs. Pair owns 32 rows; warp q computes ALL 4
// gates for hidden [64q, 64q+64). Each B fragment feeds 4 MMAs (2 m-tiles x 2
// n-halves) -> half the B-ldsm traffic of the M=16 layout.
__global__ __launch_bounds__(256, 1)
void k_lstm(const int* __restrict__ wid_g, const int* __restrict__ len_g,
            const float* __restrict__ Whh) {
    extern __shared__ char sm[];
    const u32 sb = s2u(sm);
    const int tid = threadIdx.x, lane = tid & 31, w = tid >> 5;
    const int gid = lane >> 2, t4 = lane & 3;
    const int pair = w >> 1, q = w & 1;
    const int base = blockIdx.x * 128;
    const int prow = pair * 32;

    // W_hh -> f16 swizzled smem
    for (int i = tid; i < 32768; i += 256) {
        int j = i >> 6, kp = i & 63;
        float2 wv = *(const float2*)(Whh + j * 128 + kp * 2);
        u32 o = (u32)(j * 256 + kp * 4);
        *(__half2*)(sm + SM_W + (o ^ ((o >> 4) & 0x70))) = __floats2half2_rn(wv.x, wv.y);
    }
    // H zero
    for (int i = tid; i < 2048; i += 256)
        ((uint4*)(sm + SM_H))[i] = make_uint4(0, 0, 0, 0);
    if (tid < 128)
        ((unsigned char*)(sm + SM_LEN))[tid] = (unsigned char)len_g[g_perm[base + tid]];
    for (int i = tid; i < 2048; i += 256) {
        int r = i >> 4, t = i & 15;
        ((unsigned char*)(sm + SM_WID))[i] = (unsigned char)wid_g[g_perm[base + r] * 16 + t];
    }
    __syncthreads();

    const unsigned char* LEN = (const unsigned char*)(sm + SM_LEN);
    const unsigned char* WID = (const unsigned char*)(sm + SM_WID);
    int lenr[2][2];   // [mt][rs]
#pragma unroll
    for (int mt = 0; mt < 2; ++mt) {
        lenr[mt][0] = LEN[prow + 16 * mt + gid];
        lenr[mt][1] = LEN[prow + 16 * mt + gid + 8];
    }
    const int tw = LEN[prow];   // sorted desc: pair max

    // B (W) addressing
    const int jl = (lane & 7) + ((lane >> 4) << 3);
    const u32 wka = (u32)(((lane >> 3) & 1) << 4);
    const u32 wmask = (u32)((lane & 7) << 4);
    const u32 Bbase = sb + SM_W + (u32)(64 * q + jl) * 256;

    // A (H) ldmatrix addressing
    const int arow = (lane & 7) + (((lane >> 3) & 1) << 3);
    const u32 xorr = (u32)((lane & 7) << 4);
    const u32 Abase = sb + SM_H + (u32)(prow + arow) * 256;
    const u32 aka = (u32)(((lane >> 4) & 1) << 4);

    // H write addressing: Hw[mt][rs]
    const u32 g4 = (u32)(gid << 4);
    const u32 Hw00 = (u32)SM_H + (u32)(prow + gid) * 256 + (u32)(128 * q + 4 * t4);
    // packed-G per-thread inner offset (gmem, L2-resident)
    const u32 gq = (u32)(512 * q + 8 * t4);

    float c_[4][2][2][2][2];   // [st][b][mt][rs][e]
#pragma unroll
    for (int st = 0; st < 4; ++st)
#pragma unroll
        for (int b = 0; b < 2; ++b)
#pragma unroll
            for (int mt = 0; mt < 2; ++mt) {
                c_[st][b][mt][0][0] = 0.f; c_[st][b][mt][0][1] = 0.f;
                c_[st][b][mt][1][0] = 0.f; c_[st][b][mt][1][1] = 0.f;
            }

    // ---------- t = 0 peeled: h == 0, gates = G only ----------
    {
#pragma unroll
        for (int mt = 0; mt < 2; ++mt) {
            const unsigned char* gp0 = g_Gh + WID[(prow + 16 * mt + gid) * 16] * 1032 + gq;
            const unsigned char* gp1 = g_Gh + WID[(prow + 16 * mt + gid + 8) * 16] * 1032 + gq;
#pragma unroll
            for (int st = 0; st < 4; ++st) {
                uint2 ui0 = *(const uint2*)(gp0 + st * 128);
                uint2 ug0 = *(const uint2*)(gp0 + st * 128 + 64);
                uint2 uo0 = *(const uint2*)(gp0 + st * 128 + 96);
                uint2 ui1 = *(const uint2*)(gp1 + st * 128);
                uint2 ug1 = *(const uint2*)(gp1 + st * 128 + 64);
                uint2 uo1 = *(const uint2*)(gp1 + st * 128 + 96);
#pragma unroll
                for (int b = 0; b < 2; ++b)
#pragma unroll
                    for (int rs = 0; rs < 2; ++rs) {
                        u32 xi = rs ? (b ? ui1.y : ui1.x) : (b ? ui0.y : ui0.x);
                        u32 xg = rs ? (b ? ug1.y : ug1.x) : (b ? ug0.y : ug0.x);
                        u32 xo = rs ? (b ? uo1.y : uo1.x) : (b ? uo0.y : uo0.x);
                        u32 ig = mul2(sig2(xi), tanh2(xg));
                        float2 ig2 = h22f2(ig);
                        c_[st][b][mt][rs][0] = ig2.x;
                        c_[st][b][mt][rs][1] = ig2.y;
                        u32 hn = mul2(sig2(xo), tanh2(ig));
                        *(u32*)(sm + Hw00 + (u32)(4096 * mt + 2048 * rs)
                                + ((u32)(32 * st + 16 * b) ^ g4)) = hn;
                    }
            }
        }
        asm volatile("bar.sync %0, 64;" :: "r"(pair + 1) : "memory");  // writes done
    }

    // ---------- t >= 1 ----------
    for (int t = 1; t < tw; ++t) {
        const unsigned char* gp[2][2];
#pragma unroll
        for (int mt = 0; mt < 2; ++mt) {
            gp[mt][0] = g_Gh + WID[(prow + 16 * mt + gid) * 16 + t] * 1032 + gq;
            gp[mt][1] = g_Gh + WID[(prow + 16 * mt + gid + 8) * 16 + t] * 1032 + gq;
        }

        u32 A[2][8][4];
#pragma unroll
        for (int mt = 0; mt < 2; ++mt)
#pragma unroll
            for (int kc = 0; kc < 8; ++kc)
                ldsm4(A[mt][kc], Abase + (u32)(4096 * mt) + (((u32)(kc * 32) + aka) ^ xorr));
        asm volatile("bar.sync %0, 64;" :: "r"(pair + 1) : "memory");  // reads done

#pragma unroll
        for (int st = 0; st < 4; ++st) {
            float acc[4][2][2][4];   // [gate][b][mt][rs*2+e]
#pragma unroll
            for (int g = 0; g < 4; ++g)
#pragma unroll
                for (int mt = 0; mt < 2; ++mt) {
                    uint2 u0 = *(const uint2*)(gp[mt][0] + st * 128 + g * 32);
                    uint2 u1 = *(const uint2*)(gp[mt][1] + st * 128 + g * 32);
                    float2 a0 = h22f2(u0.x), b0 = h22f2(u0.y);
                    float2 a1 = h22f2(u1.x), b1 = h22f2(u1.y);
                    acc[g][0][mt][0] = a0.x; acc[g][0][mt][1] = a0.y;
                    acc[g][1][mt][0] = b0.x; acc[g][1][mt][1] = b0.y;
                    acc[g][0][mt][2] = a1.x; acc[g][0][mt][3] = a1.y;
                    acc[g][1][mt][2] = b1.x; acc[g][1][mt][3] = b1.y;
                }
#pragma unroll
            for (int kc = 0; kc < 8; ++kc)
#pragma unroll
                for (int g = 0; g < 4; ++g) {
                    u32 B[4];
                    ldsm4(B, Bbase + (u32)(32768 * g + 4096 * st)
                               + (((u32)(kc * 32) + wka) ^ wmask));
                    mma16816(acc[g][0][0], A[0][kc], B);
                    mma16816(acc[g][1][0], A[0][kc], B + 2);
                    mma16816(acc[g][0][1], A[1][kc], B);
                    mma16816(acc[g][1][1], A[1][kc], B + 2);
                }
            // epilogue: f16x2 activations, c kept f32
#pragma unroll
            for (int b = 0; b < 2; ++b)
#pragma unroll
                for (int mt = 0; mt < 2; ++mt)
#pragma unroll
                    for (int rs = 0; rs < 2; ++rs) {
                        if (t < lenr[mt][rs]) {
                            u32 xi = packh2(acc[0][b][mt][rs * 2], acc[0][b][mt][rs * 2 + 1]);
                            u32 xf = packh2(acc[1][b][mt][rs * 2], acc[1][b][mt][rs * 2 + 1]);
                            u32 xg = packh2(acc[2][b][mt][rs * 2], acc[2][b][mt][rs * 2 + 1]);
                            u32 xo = packh2(acc[3][b][mt][rs * 2], acc[3][b][mt][rs * 2 + 1]);
                            u32 ig = mul2(sig2(xi), tanh2(xg));
                            float2 f2 = h22f2(sig2(xf));
                            float2 ig2 = h22f2(ig);
                            float c0 = fmaf(f2.x, c_[st][b][mt][rs][0], ig2.x);
                            float c1 = fmaf(f2.y, c_[st][b][mt][rs][1], ig2.y);
                            c_[st][b][mt][rs][0] = c0; c_[st][b][mt][rs][1] = c1;
                            u32 hn = mul2(sig2(xo), tanh2(packh2(c0, c1)));
                            *(u32*)(sm + Hw00 + (u32)(4096 * mt + 2048 * rs)
                                    + ((u32)(32 * st + 16 * b) ^ g4)) = hn;
                        }
                    }
        }
        asm volatile("bar.sync %0, 64;" :: "r"(pair + 1) : "memory");  // writes done
    }

    // reps = final cell state (f16)
#pragma unroll
    for (int mt = 0; mt < 2; ++mt)
#pragma unroll
        for (int rs = 0; rs < 2; ++rs) {
            int bn = g_perm[base + prow + 16 * mt + gid + 8 * rs];
            __half* dst = g_reps_h + (size_t)bn * HH + 64 * q + 2 * t4;
#pragma unroll
            for (int st = 0; st < 4; ++st)
#pragma unroll
                for (int b = 0; b < 2; ++b)
                    *(u32*)(dst + 16 * st + 8 * b) =
                        packh2(c_[st][b][mt][rs][0], c_[st][b][mt][rs][1]);
        }
}

// ---- head: cos 4x4 -> conv1 relu -> conv2 relu -> scorer -> sigmoid ----
__global__ void k_head(const float* __restrict__ c1w, const float* __restrict__ c1b,
                       const float* __restrict__ c2w, const float* __restrict__ c2b,
                       const float* __restrict__ scw, const float* __restrict__ scb,
                       float* __restrict__ out) {
    int gw = blockIdx.x * 8 + (threadIdx.x >> 5);
    int lane = threadIdx.x & 31;
    if (gw >= BB) return;
    const __half* rp = g_reps_h + (size_t)gw * (NW * HH);
    float rv[4][4];
#pragma unroll
    for (int i = 0; i < 4; ++i) {
        uint2 u = *(const uint2*)(rp + i * HH + lane * 4);
        float2 lo = h22f2(u.x), hi = h22f2(u.y);
        rv[i][0] = lo.x; rv[i][1] = lo.y; rv[i][2] = hi.x; rv[i][3] = hi.y;
    }
    const int pi[10] = {0,0,0,0,1,1,1,2,2,3};
    const int pj[10] = {0,1,2,3,1,2,3,2,3,3};
    float dots[10];
#pragma unroll
    for (int d = 0; d < 10; ++d) {
        float s = rv[pi[d]][0]*rv[pj[d]][0] + rv[pi[d]][1]*rv[pj[d]][1]
                + rv[pi[d]][2]*rv[pj[d]][2] + rv[pi[d]][3]*rv[pj[d]][3];
#pragma unroll
        for (int o = 16; o; o >>= 1) s += __shfl_xor_sync(0xffffffffu, s, o);
        dots[d] = s;
    }
    if (lane) return;
    float nn[4] = { rsqrtf(dots[0]), rsqrtf(dots[4]), rsqrtf(dots[7]), rsqrtf(dots[9]) };
    const int dmap[4][4] = {{0,1,2,3},{1,4,5,6},{2,5,7,8},{3,6,8,9}};
    float cm[4][4];
#pragma unroll
    for (int i = 0; i < 4; ++i)
#pragma unroll
        for (int j = 0; j < 4; ++j)
            cm[i][j] = dots[dmap[i][j]] * nn[i] * nn[j];
    float o1[4][3][3];
#pragma unroll
    for (int cc = 0; cc < 4; ++cc) {
        float w00 = c1w[cc*4+0], w01 = c1w[cc*4+1], w10 = c1w[cc*4+2], w11 = c1w[cc*4+3];
        float bb = c1b[cc];
#pragma unroll
        for (int y = 0; y < 3; ++y)
#pragma unroll
            for (int x = 0; x < 3; ++x)
                o1[cc][y][x] = fmaxf(bb + w00*cm[y][x] + w01*cm[y][x+1]
                                        + w10*cm[y+1][x] + w11*cm[y+1][x+1], 0.f);
    }
    float score = scb[0];
#pragma unroll
    for (int oc = 0; oc < 8; ++oc) {
        float bb = c2b[oc];
#pragma unroll
        for (int y = 0; y < 2; ++y)
#pragma unroll
            for (int x = 0; x < 2; ++x) {
                float s = bb;
#pragma unroll
                for (int ic = 0; ic < 4; ++ic) {
                    const float* ww = c2w + ((oc*4 + ic) * 4);
                    s += ww[0]*o1[ic][y][x]   + ww[1]*o1[ic][y][x+1]
                       + ww[2]*o1[ic][y+1][x] + ww[3]*o1[ic][y+1][x+1];
                }
                score += fmaxf(s, 0.f) * scw[oc*4 + y*2 + x];
            }
    }
    out[gw] = sigm_exact(score);
}

extern "C" void kernel_launch(void* const* d_in, const int* in_sizes, int n_in,
                              void* d_out, int out_size) {
    const int*   word_ids = (const int*)  d_in[0];
    const int*   lengths  = (const int*)  d_in[1];
    const float* emb      = (const float*)d_in[2];
    const float* Wih      = (const float*)d_in[3];
    const float* Whh      = (const float*)d_in[4];
    const float* bih      = (const float*)d_in[5];
    const float* bhh      = (const float*)d_in[6];
    const float* c1w      = (const float*)d_in[7];
    const float* c1b      = (const float*)d_in[8];
    const float* c2w      = (const float*)d_in[9];
    const float* c2b      = (const float*)d_in[10];
    const float* scw      = (const float*)d_in[11];
    const float* scb      = (const float*)d_in[12];
    float* out = (float*)d_out;

    static int attr_done = 0;
    if (!attr_done) {
        cudaFuncSetAttribute(k_lstm, cudaFuncAttributeMaxDynamicSharedMemorySize, SM_BYTES);
        attr_done = 1;
    }
    k_pre1<<<128, 512>>>(lengths, emb, Wih, bih, bhh);
    k_scatter<<<128, 256>>>(lengths);
    k_lstm<<<BN_TOT/128, 256, SM_BYTES>>>(word_ids, lengths, Whh);
    k_head<<<BB/8, 256>>>(c1w, c1b, c2w, c2b, scw, scb, out);
}

// round 17
// speedup vs baseline: 1.0112x; 1.0112x over previous
#include <cuda_runtime.h>
#include <cuda_fp16.h>

#define BB 8192
#define NW 4
#define LL 16
#define EE 128
#define HH 128
#define VV 64
#define BN_TOT (BB*NW)
#define G4H 512

typedef unsigned int u32;

// G pre-packed f16, fragment-major: off = v*1032 + q*512 + st*128 + g*32 + t4*8 + b*4 + e*2
__device__ __align__(16) unsigned char g_Gh[VV * 1032];
__device__ __align__(16) __half g_reps_h[(size_t)BN_TOT * HH];
__device__ int g_perm[BN_TOT];
__device__ int g_cursor[16];
__device__ int g_hist[16];
__device__ unsigned int g_tick;

// ---- dynamic smem map (bytes) ----
#define SM_W    0          // W_hh f16 [512][128], 256B rows, XOR swizzle   (131072)
#define SM_H    131072     // h f16 [128][128], 256B rows, XOR swizzle      (32768)
#define SM_WID  163840     // u8 [128][16]                                  (2048)
#define SM_LEN  165888     // u8 [128]
#define SM_BYTES 166016

__device__ __forceinline__ float sigm_exact(float x) { return __fdividef(1.f, 1.f + __expf(-x)); }

__device__ __forceinline__ u32 s2u(const void* p) {
    u32 a; asm("{.reg .u64 t; cvta.to.shared.u64 t, %1; cvt.u32.u64 %0, t;}" : "=r"(a) : "l"(p));
    return a;
}
__device__ __forceinline__ void ldsm4(u32* r, u32 addr) {
    asm volatile("ldmatrix.sync.aligned.m8n8.x4.shared.b16 {%0,%1,%2,%3}, [%4];"
        : "=r"(r[0]), "=r"(r[1]), "=r"(r[2]), "=r"(r[3]) : "r"(addr));
}
// f16-accumulator HMMA: D/C are 2x u32 (4 f16), pre-packed in epilogue layout
__device__ __forceinline__ void mma16816h(u32* c, const u32* a, const u32* b) {
    asm volatile("mma.sync.aligned.m16n8k16.row.col.f16.f16.f16.f16 "
        "{%0,%1}, {%2,%3,%4,%5}, {%6,%7}, {%0,%1};"
        : "+r"(c[0]), "+r"(c[1])
        : "r"(a[0]), "r"(a[1]), "r"(a[2]), "r"(a[3]), "r"(b[0]), "r"(b[1]));
}
__device__ __forceinline__ u32 packh2(float a, float b) {
    __half2 h = __floats2half2_rn(a, b);
    return *(u32*)&h;
}
__device__ __forceinline__ float2 h22f2(u32 x) { return __half22float2(*(__half2*)&x); }
__device__ __forceinline__ u32 tanh2(u32 x) {
    u32 y; asm("tanh.approx.f16x2 %0, %1;" : "=r"(y) : "r"(x)); return y;
}
__device__ __forceinline__ u32 mul2(u32 a, u32 b) {
    __half2 r = __hmul2(*(__half2*)&a, *(__half2*)&b); return *(u32*)&r;
}
__device__ __forceinline__ u32 sig2(u32 x) {   // sigmoid(x) = 0.5*tanh(0.5x)+0.5, f16x2
    const u32 k05 = 0x38003800u;
    u32 t = tanh2(mul2(x, k05));
    __half2 r = __hfma2(*(__half2*)&t, *(__half2*)&k05, *(__half2*)&k05);
    return *(u32*)&r;
}

// ---- fused: blocks 0..63 packed G; blocks 64..127 histogram; last block scans ----
__global__ void k_pre1(const int* __restrict__ lengths,
                       const float* __restrict__ emb, const float* __restrict__ Wih,
                       const float* __restrict__ bih, const float* __restrict__ bhh) {
    int tid = threadIdx.x;
    if (blockIdx.x < 64) {
        int v = blockIdx.x, j = tid;
        const float* e = emb + v * EE;
        const float* w = Wih + j * EE;
        float s = bih[j] + bhh[j];
#pragma unroll 8
        for (int k = 0; k < EE; ++k) s = fmaf(e[k], w[k], s);
        int g = j >> 7, q = (j >> 6) & 1, u = j & 63;
        int st = u >> 4, b = (u >> 3) & 1, t4 = (u >> 1) & 3, ee = u & 1;
        int off = v * 1032 + q * 512 + st * 128 + g * 32 + t4 * 8 + b * 4 + ee * 2;
        *(__half*)(g_Gh + off) = __float2half_rn(s);
    } else {
        __shared__ int sh[16];
        if (tid < 16) sh[tid] = 0;
        __syncthreads();
        int bn = (blockIdx.x - 64) * 512 + tid;
        atomicAdd(&sh[16 - lengths[bn]], 1);
        __syncthreads();
        if (tid < 16) atomicAdd(&g_hist[tid], sh[tid]);
        __syncthreads();
        if (tid == 0 && (atomicAdd(&g_tick, 1u) & 63u) == 63u) {
            int cum = 0;
            for (int b2 = 0; b2 < 16; ++b2) {
                g_cursor[b2] = cum; cum += g_hist[b2]; g_hist[b2] = 0;
            }
        }
    }
}

__global__ void k_scatter(const int* __restrict__ lengths) {
    __shared__ int cnt[16], base[16];
    int tid = threadIdx.x;
    if (tid < 16) cnt[tid] = 0;
    __syncthreads();
    int bn = blockIdx.x * 256 + tid;
    int bin = 16 - lengths[bn];
    int rank = atomicAdd(&cnt[bin], 1);
    __syncthreads();
    if (tid < 16) base[tid] = atomicAdd(&g_cursor[tid], cnt[tid]);
    __syncthreads();
    g_perm[base[bin] + rank] = bn;
}

// ---- HMMA LSTM: M=16/warp, 512 threads, f16 accumulators ----
// CTA = 128 rows, 16 warps = 8 pairs. Pair owns 16 rows; warp q computes ALL 4
// gates for hidden [64q, 64q+64). f16-acc MMA: D arrives pre-packed f16x2 in
// exactly the layout the f16x2 activation path consumes; c stays f32 in regs.
__global__ __launch_bounds__(512, 1)
void k_lstm(const int* __restrict__ wid_g, const int* __restrict__ len_g,
            const float* __restrict__ Whh) {
    extern __shared__ char sm[];
    const u32 sb = s2u(sm);
    const int tid = threadIdx.x, lane = tid & 31, w = tid >> 5;
    const int gid = lane >> 2, t4 = lane & 3;
    const int pair = w >> 1, q = w & 1;
    const int base = blockIdx.x * 128;
    const int prow = pair * 16;

    // W_hh -> f16 swizzled smem
    for (int i = tid; i < 32768; i += 512) {
        int j = i >> 6, kp = i & 63;
        float2 wv = *(const float2*)(Whh + j * 128 + kp * 2);
        u32 o = (u32)(j * 256 + kp * 4);
        *(__half2*)(sm + SM_W + (o ^ ((o >> 4) & 0x70))) = __floats2half2_rn(wv.x, wv.y);
    }
    // H zero
    for (int i = tid; i < 2048; i += 512)
        ((uint4*)(sm + SM_H))[i] = make_uint4(0, 0, 0, 0);
    if (tid < 128)
        ((unsigned char*)(sm + SM_LEN))[tid] = (unsigned char)len_g[g_perm[base + tid]];
    for (int i = tid; i < 2048; i += 512) {
        int r = i >> 4, t = i & 15;
        ((unsigned char*)(sm + SM_WID))[i] = (unsigned char)wid_g[g_perm[base + r] * 16 + t];
    }
    __syncthreads();

    const unsigned char* LEN = (const unsigned char*)(sm + SM_LEN);
    const unsigned char* WID = (const unsigned char*)(sm + SM_WID);
    int lenr[2];
    lenr[0] = LEN[prow + gid];
    lenr[1] = LEN[prow + gid + 8];
    const int tw = LEN[prow];   // sorted desc: pair max

    // B (W) addressing
    const int jl = (lane & 7) + ((lane >> 4) << 3);
    const u32 wka = (u32)(((lane >> 3) & 1) << 4);
    const u32 wmask = (u32)((lane & 7) << 4);
    const u32 Bbase = sb + SM_W + (u32)(64 * q + jl) * 256;

    // A (H) ldmatrix addressing
    const int arow = (lane & 7) + (((lane >> 3) & 1) << 3);
    const u32 xorr = (u32)((lane & 7) << 4);
    const u32 Abase = sb + SM_H + (u32)(prow + arow) * 256;
    const u32 aka = (u32)(((lane >> 4) & 1) << 4);

    // H write addressing
    const u32 g4 = (u32)(gid << 4);
    const u32 Hw0 = (u32)SM_H + (u32)(prow + gid) * 256 + (u32)(128 * q + 4 * t4);
    const u32 Hw1 = Hw0 + 8 * 256;
    // packed-G per-thread inner offset (gmem, L2-resident)
    const u32 gq = (u32)(512 * q + 8 * t4);

    float c_[4][2][2][2];   // [st][b][rs][e]
#pragma unroll
    for (int st = 0; st < 4; ++st)
#pragma unroll
        for (int b = 0; b < 2; ++b) {
            c_[st][b][0][0] = 0.f; c_[st][b][0][1] = 0.f;
            c_[st][b][1][0] = 0.f; c_[st][b][1][1] = 0.f;
        }

    // ---------- t = 0 peeled: h == 0, gates = G only ----------
    {
        const unsigned char* gp0 = g_Gh + WID[(prow + gid) * 16] * 1032 + gq;
        const unsigned char* gp1 = g_Gh + WID[(prow + gid + 8) * 16] * 1032 + gq;
#pragma unroll
        for (int st = 0; st < 4; ++st) {
            uint2 ui0 = *(const uint2*)(gp0 + st * 128);
            uint2 ug0 = *(const uint2*)(gp0 + st * 128 + 64);
            uint2 uo0 = *(const uint2*)(gp0 + st * 128 + 96);
            uint2 ui1 = *(const uint2*)(gp1 + st * 128);
            uint2 ug1 = *(const uint2*)(gp1 + st * 128 + 64);
            uint2 uo1 = *(const uint2*)(gp1 + st * 128 + 96);
#pragma unroll
            for (int b = 0; b < 2; ++b)
#pragma unroll
                for (int rs = 0; rs < 2; ++rs) {
                    u32 xi = rs ? (b ? ui1.y : ui1.x) : (b ? ui0.y : ui0.x);
                    u32 xg = rs ? (b ? ug1.y : ug1.x) : (b ? ug0.y : ug0.x);
                    u32 xo = rs ? (b ? uo1.y : uo1.x) : (b ? uo0.y : uo0.x);
                    u32 ig = mul2(sig2(xi), tanh2(xg));
                    float2 ig2 = h22f2(ig);
                    c_[st][b][rs][0] = ig2.x;
                    c_[st][b][rs][1] = ig2.y;
                    u32 hn = mul2(sig2(xo), tanh2(ig));
                    *(u32*)(sm + (rs ? Hw1 : Hw0) + ((u32)(32 * st + 16 * b) ^ g4)) = hn;
                }
        }
        asm volatile("bar.sync %0, 64;" :: "r"(pair + 1) : "memory");  // writes done
    }

    // ---------- t >= 1 ----------
    for (int t = 1; t < tw; ++t) {
        const unsigned char* gp0 = g_Gh + WID[(prow + gid) * 16 + t] * 1032 + gq;
        const unsigned char* gp1 = g_Gh + WID[(prow + gid + 8) * 16 + t] * 1032 + gq;

        u32 A[8][4];
#pragma unroll
        for (int kc = 0; kc < 8; ++kc)
            ldsm4(A[kc], Abase + (((u32)(kc * 32) + aka) ^ xorr));
        asm volatile("bar.sync %0, 64;" :: "r"(pair + 1) : "memory");  // reads done

#pragma unroll
        for (int st = 0; st < 4; ++st) {
            // f16 accumulators, initialized with G (already packed in frag layout)
            u32 acc[4][2][2];   // [gate][b(n8 half)][rs]
#pragma unroll
            for (int g = 0; g < 4; ++g) {
                uint2 u0 = *(const uint2*)(gp0 + st * 128 + g * 32);
                uint2 u1 = *(const uint2*)(gp1 + st * 128 + g * 32);
                acc[g][0][0] = u0.x; acc[g][0][1] = u1.x;
                acc[g][1][0] = u0.y; acc[g][1][1] = u1.y;
            }
#pragma unroll
            for (int kc = 0; kc < 8; ++kc)
#pragma unroll
                for (int g = 0; g < 4; ++g) {
                    u32 B[4];
                    ldsm4(B, Bbase + (u32)(32768 * g + 4096 * st)
                               + (((u32)(kc * 32) + wka) ^ wmask));
                    mma16816h(acc[g][0], A[kc], B);
                    mma16816h(acc[g][1], A[kc], B + 2);
                }
            // epilogue: gates arrive pre-packed f16x2; c kept f32
#pragma unroll
            for (int b = 0; b < 2; ++b)
#pragma unroll
                for (int rs = 0; rs < 2; ++rs) {
                    if (t < lenr[rs]) {
                        u32 ig = mul2(sig2(acc[0][b][rs]), tanh2(acc[2][b][rs]));
                        float2 f2 = h22f2(sig2(acc[1][b][rs]));
                        float2 ig2 = h22f2(ig);
                        float c0 = fmaf(f2.x, c_[st][b][rs][0], ig2.x);
                        float c1 = fmaf(f2.y, c_[st][b][rs][1], ig2.y);
                        c_[st][b][rs][0] = c0; c_[st][b][rs][1] = c1;
                        u32 hn = mul2(sig2(acc[3][b][rs]), tanh2(packh2(c0, c1)));
                        *(u32*)(sm + (rs ? Hw1 : Hw0) + ((u32)(32 * st + 16 * b) ^ g4)) = hn;
                    }
                }
        }
        asm volatile("bar.sync %0, 64;" :: "r"(pair + 1) : "memory");  // writes done
    }

    // reps = final cell state (f16)
#pragma unroll
    for (int rs = 0; rs < 2; ++rs) {
        int bn = g_perm[base + prow + gid + 8 * rs];
        __half* dst = g_reps_h + (size_t)bn * HH + 64 * q + 2 * t4;
#pragma unroll
        for (int st = 0; st < 4; ++st)
#pragma unroll
            for (int b = 0; b < 2; ++b)
                *(u32*)(dst + 16 * st + 8 * b) =
                    packh2(c_[st][b][rs][0], c_[st][b][rs][1]);
    }
}

// ---- head: cos 4x4 -> conv1 relu -> conv2 relu -> scorer -> sigmoid ----
__global__ void k_head(const float* __restrict__ c1w, const float* __restrict__ c1b,
                       const float* __restrict__ c2w, const float* __restrict__ c2b,
                       const float* __restrict__ scw, const float* __restrict__ scb,
                       float* __restrict__ out) {
    int gw = blockIdx.x * 8 + (threadIdx.x >> 5);
    int lane = threadIdx.x & 31;
    if (gw >= BB) return;
    const __half* rp = g_reps_h + (size_t)gw * (NW * HH);
    float rv[4][4];
#pragma unroll
    for (int i = 0; i < 4; ++i) {
        uint2 u = *(const uint2*)(rp + i * HH + lane * 4);
        float2 lo = h22f2(u.x), hi = h22f2(u.y);
        rv[i][0] = lo.x; rv[i][1] = lo.y; rv[i][2] = hi.x; rv[i][3] = hi.y;
    }
    const int pi[10] = {0,0,0,0,1,1,1,2,2,3};
    const int pj[10] = {0,1,2,3,1,2,3,2,3,3};
    float dots[10];
#pragma unroll
    for (int d = 0; d < 10; ++d) {
        float s = rv[pi[d]][0]*rv[pj[d]][0] + rv[pi[d]][1]*rv[pj[d]][1]
                + rv[pi[d]][2]*rv[pj[d]][2] + rv[pi[d]][3]*rv[pj[d]][3];
#pragma unroll
        for (int o = 16; o; o >>= 1) s += __shfl_xor_sync(0xffffffffu, s, o);
        dots[d] = s;
    }
    if (lane) return;
    float nn[4] = { rsqrtf(dots[0]), rsqrtf(dots[4]), rsqrtf(dots[7]), rsqrtf(dots[9]) };
    const int dmap[4][4] = {{0,1,2,3},{1,4,5,6},{2,5,7,8},{3,6,8,9}};
    float cm[4][4];
#pragma unroll
    for (int i = 0; i < 4; ++i)
#pragma unroll
        for (int j = 0; j < 4; ++j)
            cm[i][j] = dots[dmap[i][j]] * nn[i] * nn[j];
    float o1[4][3][3];
#pragma unroll
    for (int cc = 0; cc < 4; ++cc) {
        float w00 = c1w[cc*4+0], w01 = c1w[cc*4+1], w10 = c1w[cc*4+2], w11 = c1w[cc*4+3];
        float bb = c1b[cc];
#pragma unroll
        for (int y = 0; y < 3; ++y)
#pragma unroll
            for (int x = 0; x < 3; ++x)
                o1[cc][y][x] = fmaxf(bb + w00*cm[y][x] + w01*cm[y][x+1]
                                        + w10*cm[y+1][x] + w11*cm[y+1][x+1], 0.f);
    }
    float score = scb[0];
#pragma unroll
    for (int oc = 0; oc < 8; ++oc) {
        float bb = c2b[oc];
#pragma unroll
        for (int y = 0; y < 2; ++y)
#pragma unroll
            for (int x = 0; x < 2; ++x) {
                float s = bb;
#pragma unroll
                for (int ic = 0; ic < 4; ++ic) {
                    const float* ww = c2w + ((oc*4 + ic) * 4);
                    s += ww[0]*o1[ic][y][x]   + ww[1]*o1[ic][y][x+1]
                       + ww[2]*o1[ic][y+1][x] + ww[3]*o1[ic][y+1][x+1];
                }
                score += fmaxf(s, 0.f) * scw[oc*4 + y*2 + x];
            }
    }
    out[gw] = sigm_exact(score);
}

extern "C" void kernel_launch(void* const* d_in, const int* in_sizes, int n_in,
                              void* d_out, int out_size) {
    const int*   word_ids = (const int*)  d_in[0];
    const int*   lengths  = (const int*)  d_in[1];
    const float* emb      = (const float*)d_in[2];
    const float* Wih      = (const float*)d_in[3];
    const float* Whh      = (const float*)d_in[4];
    const float* bih      = (const float*)d_in[5];
    const float* bhh      = (const float*)d_in[6];
    const float* c1w      = (const float*)d_in[7];
    const float* c1b      = (const float*)d_in[8];
    const float* c2w      = (const float*)d_in[9];
    const float* c2b      = (const float*)d_in[10];
    const float* scw      = (const float*)d_in[11];
    const float* scb      = (const float*)d_in[12];
    float* out = (float*)d_out;

    static int attr_done = 0;
    if (!attr_done) {
        cudaFuncSetAttribute(k_lstm, cudaFuncAttributeMaxDynamicSharedMemorySize, SM_BYTES);
        attr_done = 1;
    }
    k_pre1<<<128, 512>>>(lengths, emb, Wih, bih, bhh);
    k_scatter<<<128, 256>>>(lengths);
    k_lstm<<<BN_TOT/128, 512, SM_BYTES>>>(word_ids, lengths, Whh);
    k_head<<<BB/8, 256>>>(c1w, c1b, c2w, c2b, scw, scb, out);
}